// round 3
// baseline (speedup 1.0000x reference)
#include <cuda_runtime.h>
#include <math.h>

#define C_ 10
#define Q_ 1000
#define R_ 1024
#define N_ 512
#define S_ 10000
#define CQ 10000
#define SPLITK 10
#define KCH 1000

// ---------------- static device scratch ----------------
__device__ float g_X[CQ * R_];                         // centered data (40MB)
__device__ float g_Spart[SPLITK * 36 * 128 * 128];     // gram partials (23.6MB)
__device__ float g_S[R_ * R_];                         // sigma -> L in lower tri
__device__ float g_mu[C_ * R_];
__device__ float g_scores[N_ * C_];
__device__ float g_svos[C_ * C_];
__device__ float g_vos[C_ * R_];
__device__ int   g_list[C_ * N_];
__device__ int   g_kc[C_];
__device__ unsigned long long g_amax[C_];
__device__ float g_cls_part[N_];
__device__ float g_bce[N_ + C_];

// ---------------- helpers ----------------
__device__ __forceinline__ unsigned long long dup2(float a) {
    unsigned long long r; asm("mov.b64 %0, {%1, %1};" : "=l"(r) : "f"(a)); return r;
}
__device__ __forceinline__ void fma2(unsigned long long& d, unsigned long long a, unsigned long long b) {
    asm("fma.rn.f32x2 %0, %1, %2, %0;" : "+l"(d) : "l"(a), "l"(b));
}
union F4U { float4 f4; unsigned long long u[2]; float f[4]; };

__device__ __forceinline__ void tri_decode(int t, int& i, int& j) {
    int ti = (int)((sqrtf(8.f * (float)t + 1.f) - 1.f) * 0.5f);
    while ((ti + 1) * (ti + 2) / 2 <= t) ti++;
    while (ti * (ti + 1) / 2 > t) ti--;
    i = ti; j = t - ti * (ti + 1) / 2;
}

// ---------------- per-class ordered sample lists + amax reset ----------------
__global__ void k_lists(const int* __restrict__ labels) {
    __shared__ int lab[N_];
    int tid = threadIdx.x;
    if (tid < N_) lab[tid] = labels[tid];
    __syncthreads();
    if (tid < C_) {
        g_amax[tid] = 0ull;
        int k = 0;
        for (int n = 0; n < N_; n++) if (lab[n] == tid) g_list[tid * N_ + (k++)] = n;
        g_kc[tid] = k;
    }
}

// ---------------- scores + focal loss ----------------
__global__ void k_scores_cls(const float* __restrict__ box, const float* __restrict__ Wp,
                             const float* __restrict__ bp, const int* __restrict__ labels) {
    int n = blockIdx.x; int wid = threadIdx.x >> 5; int lane = threadIdx.x & 31;
    __shared__ float terms[C_];
    const float4* f = (const float4*)(box + (size_t)n * R_);
    const float4* w = (const float4*)(Wp + (size_t)wid * R_);
    float s = 0.f;
#pragma unroll
    for (int i = 0; i < 8; i++) {
        float4 a = f[lane + i * 32]; float4 b = w[lane + i * 32];
        s += a.x * b.x + a.y * b.y + a.z * b.z + a.w * b.w;
    }
    for (int o = 16; o; o >>= 1) s += __shfl_xor_sync(0xffffffffu, s, o);
    if (lane == 0) {
        float sc = s + bp[wid];
        g_scores[n * C_ + wid] = sc;
        float t = (labels[n] == wid) ? 1.f : 0.f;
        float ce = fmaxf(sc, 0.f) - sc * t + log1pf(expf(-fabsf(sc)));
        float p = 1.f / (1.f + expf(-sc));
        float pt = p * t + (1.f - p) * (1.f - t);
        float at = 0.25f * t + 0.75f * (1.f - t);
        float om = 1.f - pt;
        terms[wid] = at * ce * om * om;
    }
    __syncthreads();
    if (threadIdx.x == 0) {
        float acc = 0.f;
#pragma unroll
        for (int c = 0; c < C_; c++) acc += terms[c];
        g_cls_part[n] = acc;
    }
}

// ---------------- per-class mean of post-update queue ----------------
__global__ void k_mu(const float* __restrict__ idd, const float* __restrict__ box) {
    int c = blockIdx.x; int r = blockIdx.y * 128 + threadIdx.x;
    int kc = g_kc[c];
    float s = 0.f;
    const float* base = idd + (size_t)c * Q_ * R_ + r;
    for (int q = kc; q < Q_; q++) s += base[(size_t)q * R_];
    for (int i = 0; i < kc; i++) s += box[(size_t)g_list[c * N_ + i] * R_ + r];
    g_mu[c * R_ + r] = s * (1.f / (float)Q_);
}

// ---------------- centered X ----------------
__global__ void k_buildX(const float* __restrict__ idd, const float* __restrict__ box) {
    int k = blockIdx.x;
    int c = k / Q_; int q = k - c * Q_;
    int kc = g_kc[c]; int q2 = q + kc;
    const float4* src;
    if (q2 < Q_) src = (const float4*)(idd + ((size_t)c * Q_ + q2) * R_);
    else         src = (const float4*)(box + (size_t)g_list[c * N_ + (q2 - Q_)] * R_);
    const float4* mu = (const float4*)(g_mu + c * R_);
    float4 v = src[threadIdx.x]; float4 m = mu[threadIdx.x];
    v.x -= m.x; v.y -= m.y; v.z -= m.z; v.w -= m.w;
    ((float4*)(g_X + (size_t)k * R_))[threadIdx.x] = v;
}

// ---------------- Gram X^T X: lower-tri 128x128 tiles, split-K, f32x2 ----------------
__global__ void __launch_bounds__(256) k_gram() {
    __shared__ float As[8][128], Bs[8][128];
    int t36 = blockIdx.x, kz = blockIdx.y;
    int ti, tj; tri_decode(t36, ti, tj);
    int tid = threadIdx.x;
    int kr = tid >> 5, cf = tid & 31;
    int tx = tid & 15, ty = tid >> 4;
    unsigned long long acc[8][4];
#pragma unroll
    for (int i = 0; i < 8; i++)
#pragma unroll
        for (int j = 0; j < 4; j++) acc[i][j] = 0ull;
    int k0 = kz * KCH;
    const float* XA = g_X + (size_t)ti * 128;
    const float* XB = g_X + (size_t)tj * 128;
    for (int kb = 0; kb < KCH; kb += 8) {
        size_t krow = (size_t)(k0 + kb + kr) * R_;
        *(float4*)&As[kr][cf * 4] = *(const float4*)&XA[krow + cf * 4];
        *(float4*)&Bs[kr][cf * 4] = *(const float4*)&XB[krow + cf * 4];
        __syncthreads();
#pragma unroll
        for (int kk = 0; kk < 8; kk++) {
            F4U a0, a1, b0, b1;
            a0.f4 = *(float4*)&As[kk][ty * 8];
            a1.f4 = *(float4*)&As[kk][ty * 8 + 4];
            b0.f4 = *(float4*)&Bs[kk][tx * 8];
            b1.f4 = *(float4*)&Bs[kk][tx * 8 + 4];
            unsigned long long bu[4] = { b0.u[0], b0.u[1], b1.u[0], b1.u[1] };
#pragma unroll
            for (int i = 0; i < 4; i++) {
                unsigned long long ad0 = dup2(a0.f[i]);
                unsigned long long ad1 = dup2(a1.f[i]);
#pragma unroll
                for (int j = 0; j < 4; j++) {
                    fma2(acc[i][j], ad0, bu[j]);
                    fma2(acc[i + 4][j], ad1, bu[j]);
                }
            }
        }
        __syncthreads();
    }
    float* outp = g_Spart + (size_t)(kz * 36 + t36) * 16384;
#pragma unroll
    for (int i = 0; i < 8; i++)
#pragma unroll
        for (int j = 0; j < 4; j++) {
            unsigned long long v = acc[i][j];
            float lo = __uint_as_float((unsigned)(v & 0xffffffffull));
            float hi = __uint_as_float((unsigned)(v >> 32));
            outp[(ty * 8 + i) * 128 + tx * 8 + 2 * j] = lo;
            outp[(ty * 8 + i) * 128 + tx * 8 + 2 * j + 1] = hi;
        }
}

// ---------------- reduce partials -> sigma (symmetric, +eps I) ----------------
__global__ void k_gram_reduce() {
    int t36 = blockIdx.x;
    int ti, tj; tri_decode(t36, ti, tj);
    for (int e = 0; e < 64; e++) {
        int idx = e * 256 + threadIdx.x;
        int r = idx >> 7, c = idx & 127;
        float s = 0.f;
#pragma unroll
        for (int kz = 0; kz < SPLITK; kz++)
            s += g_Spart[(size_t)(kz * 36 + t36) * 16384 + idx];
        float val = s / 10000.f;
        int gi = ti * 128 + r, gj = tj * 128 + c;
        if (gi == gj) val += 1e-4f;
        g_S[(size_t)gi * R_ + gj] = val;
        g_S[(size_t)gj * R_ + gi] = val;
    }
}

// ---------------- Cholesky: diag panel factor (packed lower tri in smem) ----------------
__global__ void k_chol_diag(int p) {
    __shared__ float T[128 * 129 / 2];
    int base = p * 128;
    int x = threadIdx.x, y = threadIdx.y;
    // load lower triangle
    for (int i = y; i < 128; i += 8)
        if (x <= i) T[i * (i + 1) / 2 + x] = g_S[(size_t)(base + i) * R_ + base + x];
    __syncthreads();
    for (int j = 0; j < 128; j++) {
        float ljj = 0.f;
        if (y == 0) ljj = sqrtf(T[j * (j + 1) / 2 + j]);
        __syncthreads();
        if (y == 0 && x >= j) {
            if (x == j) T[j * (j + 1) / 2 + j] = ljj;
            else T[x * (x + 1) / 2 + j] *= (1.f / ljj);
        }
        __syncthreads();
        if (x > j) {
            float lij = T[x * (x + 1) / 2 + j];
            for (int k = j + 1 + y; k <= x; k += 8)
                T[x * (x + 1) / 2 + k] -= lij * T[k * (k + 1) / 2 + j];
        }
        __syncthreads();
    }
    for (int i = y; i < 128; i += 8)
        if (x <= i) g_S[(size_t)(base + i) * R_ + base + x] = T[i * (i + 1) / 2 + x];
}

// ---------------- Cholesky: trsm (warp per row, smem column staging) ----------------
__global__ void k_trsm(int p) {
    int base = p * 128;
    int row = base + 128 + blockIdx.x * 8 + (threadIdx.x >> 5);
    int lane = threadIdx.x & 31;
    __shared__ float col[128];
    float* arow = g_S + (size_t)row * R_ + base;
    float a0 = arow[lane], a1 = arow[lane + 32], a2 = arow[lane + 64], a3 = arow[lane + 96];
    for (int j = 0; j < 128; j++) {
        __syncthreads();
        if (threadIdx.x < 128) col[threadIdx.x] = g_S[(size_t)(base + threadIdx.x) * R_ + base + j];
        __syncthreads();
        int src = j & 31, slot = j >> 5;
        float aval = (slot == 0) ? a0 : (slot == 1) ? a1 : (slot == 2) ? a2 : a3;
        float xj = __shfl_sync(0xffffffffu, aval, src) / col[j];
        if (lane == src) {
            if (slot == 0) a0 = xj; else if (slot == 1) a1 = xj;
            else if (slot == 2) a2 = xj; else a3 = xj;
        }
        if (lane > j) a0 -= xj * col[lane];
        if (lane + 32 > j) a1 -= xj * col[lane + 32];
        if (lane + 64 > j) a2 -= xj * col[lane + 64];
        if (lane + 96 > j) a3 -= xj * col[lane + 96];
    }
    arow[lane] = a0; arow[lane + 32] = a1; arow[lane + 64] = a2; arow[lane + 96] = a3;
}

// ---------------- Cholesky: syrk trailing update (64x64 tiles) ----------------
__global__ void k_syrk(int p) {
    __shared__ float As[64][17], Bs[64][17];
    int base = p * 128, trail = base + 128;
    int ti, tj; tri_decode(blockIdx.x, ti, tj);
    int gi0 = trail + ti * 64, gj0 = trail + tj * 64;
    int tid = threadIdx.x;
    int tx = tid & 15, ty = tid >> 4;
    float acc[4][4];
#pragma unroll
    for (int r = 0; r < 4; r++)
#pragma unroll
        for (int s = 0; s < 4; s++) acc[r][s] = 0.f;
    for (int kc = 0; kc < 128; kc += 16) {
        int li = tid >> 2, lk = (tid & 3) * 4;
        float4 va = *(const float4*)&g_S[(size_t)(gi0 + li) * R_ + base + kc + lk];
        float4 vb = *(const float4*)&g_S[(size_t)(gj0 + li) * R_ + base + kc + lk];
        As[li][lk] = va.x; As[li][lk + 1] = va.y; As[li][lk + 2] = va.z; As[li][lk + 3] = va.w;
        Bs[li][lk] = vb.x; Bs[li][lk + 1] = vb.y; Bs[li][lk + 2] = vb.z; Bs[li][lk + 3] = vb.w;
        __syncthreads();
#pragma unroll
        for (int kk = 0; kk < 16; kk++) {
            float a[4], b[4];
#pragma unroll
            for (int r = 0; r < 4; r++) a[r] = As[ty * 4 + r][kk];
#pragma unroll
            for (int s = 0; s < 4; s++) b[s] = Bs[tx * 4 + s][kk];
#pragma unroll
            for (int r = 0; r < 4; r++)
#pragma unroll
                for (int s = 0; s < 4; s++) acc[r][s] += a[r] * b[s];
        }
        __syncthreads();
    }
#pragma unroll
    for (int r = 0; r < 4; r++)
#pragma unroll
        for (int s = 0; s < 4; s++)
            g_S[(size_t)(gi0 + ty * 4 + r) * R_ + gj0 + tx * 4 + s] -= acc[r][s];
}

// ---------------- eps argmax of ||eps[c,s]||^2 (warp per row) ----------------
__global__ void k_eps(const float* __restrict__ eps) {
    int w = blockIdx.x * 8 + (threadIdx.x >> 5);
    int lane = threadIdx.x & 31;
    int c = w / S_, s = w - c * S_;
    const float4* row = (const float4*)(eps + (size_t)w * R_);
    float acc = 0.f;
#pragma unroll
    for (int i = 0; i < 8; i++) {
        float4 v = row[lane + i * 32];
        acc += v.x * v.x + v.y * v.y + v.z * v.z + v.w * v.w;
    }
    for (int o = 16; o; o >>= 1) acc += __shfl_xor_sync(0xffffffffu, acc, o);
    if (lane == 0) {
        unsigned long long key = ((unsigned long long)__float_as_uint(acc) << 32)
                               | (unsigned long long)(0x7FFFFFFFu - (unsigned)s);
        atomicMax(&g_amax[c], key);
    }
}

// ---------------- vos = mu + eps_sel @ L^T ----------------
__global__ void k_vos(const float* __restrict__ eps) {
    int c = blockIdx.y;
    int r = blockIdx.x * 128 + threadIdx.x;
    int idx = 0x7FFFFFFF - (int)(unsigned)(g_amax[c] & 0xffffffffull);
    const float* erow = eps + ((size_t)c * S_ + idx) * R_;
    const float* Lr = g_S + (size_t)r * R_;
    float s = 0.f;
    for (int j = 0; j <= r; j++) s += erow[j] * Lr[j];
    g_vos[c * R_ + r] = g_mu[c * R_ + r] + s;
}

// ---------------- scores_vos ----------------
__global__ void k_svos(const float* __restrict__ Wp, const float* __restrict__ bp) {
    int i = blockIdx.x, j = blockIdx.y;
    int tid = threadIdx.x;
    __shared__ float ws[4];
    float s = 0.f;
    for (int r = tid; r < R_; r += 128) s += g_vos[i * R_ + r] * Wp[(size_t)j * R_ + r];
    for (int o = 16; o; o >>= 1) s += __shfl_xor_sync(0xffffffffu, s, o);
    if ((tid & 31) == 0) ws[tid >> 5] = s;
    __syncthreads();
    if (tid == 0) g_svos[i * C_ + j] = ws[0] + ws[1] + ws[2] + ws[3] + bp[j];
}

// ---------------- energy + MLP + BCE (warp per item) ----------------
__global__ void k_energy(const float* __restrict__ we, const float* __restrict__ W1,
                         const float* __restrict__ b1, const float* __restrict__ W2,
                         const float* __restrict__ b2) {
    int item = blockIdx.x * 8 + (threadIdx.x >> 5);
    int lane = threadIdx.x & 31;
    if (item >= N_ + C_) return;
    float x = -1e30f;
    if (lane < C_) x = (item < N_) ? g_scores[item * C_ + lane] : g_svos[(item - N_) * C_ + lane];
    float m = x;
    for (int o = 16; o; o >>= 1) m = fmaxf(m, __shfl_xor_sync(0xffffffffu, m, o));
    float t = (lane < C_) ? expf(x - m) * fmaxf(we[lane], 0.f) : 0.f;
    for (int o = 16; o; o >>= 1) t += __shfl_xor_sync(0xffffffffu, t, o);
    float e = m + logf(t);
    float acc = 0.f;
    for (int j = lane; j < 512; j += 32) acc += fmaxf(e * W1[j] + b1[j], 0.f) * W2[j];
    for (int o = 16; o; o >>= 1) acc += __shfl_xor_sync(0xffffffffu, acc, o);
    if (lane == 0) {
        float l = acc + b2[0];
        float y = (item < N_) ? 1.f : 0.f;
        g_bce[item] = fmaxf(l, 0.f) - l * y + log1pf(expf(-fabsf(l)));
    }
}

// ---------------- final reduction ----------------
__global__ void k_final(float* __restrict__ out) {
    if (threadIdx.x == 0) {
        float cs = 0.f;
        for (int n = 0; n < N_; n++) cs += g_cls_part[n];
        out[0] = cs / (float)N_;
        float ds = 0.f;
        for (int i = 0; i < N_ + C_; i++) ds += g_bce[i];
        out[1] = 0.1f * ds / (float)(N_ + C_);
    }
}

extern "C" void kernel_launch(void* const* d_in, const int* in_sizes, int n_in,
                              void* d_out, int out_size) {
    const float* box = (const float*)d_in[0];
    const int* labels = (const int*)d_in[1];
    const float* idd = (const float*)d_in[2];
    const float* Wp = (const float*)d_in[4];
    const float* bp = (const float*)d_in[5];
    const float* we = (const float*)d_in[6];
    const float* W1 = (const float*)d_in[7];
    const float* b1 = (const float*)d_in[8];
    const float* W2 = (const float*)d_in[9];
    const float* b2 = (const float*)d_in[10];
    const float* eps = (const float*)d_in[11];
    float* out = (float*)d_out;

    k_lists<<<1, 512>>>(labels);
    k_scores_cls<<<N_, 320>>>(box, Wp, bp, labels);
    k_mu<<<dim3(C_, 8), 128>>>(idd, box);
    k_buildX<<<CQ, 256>>>(idd, box);
    k_gram<<<dim3(36, SPLITK), 256>>>();
    k_gram_reduce<<<36, 256>>>();
    for (int p = 0; p < 8; p++) {
        k_chol_diag<<<1, dim3(128, 8)>>>(p);
        int nrows = R_ - (p + 1) * 128;
        if (nrows > 0) {
            k_trsm<<<nrows / 8, 256>>>(p);
            int T = nrows / 64;
            k_syrk<<<T * (T + 1) / 2, 256>>>(p);
        }
    }
    k_eps<<<(C_ * S_) / 8, 256>>>(eps);
    k_vos<<<dim3(8, C_), 128>>>(eps);
    k_svos<<<dim3(C_, C_), 128>>>(Wp, bp);
    k_energy<<<(N_ + C_ + 7) / 8, 256>>>(we, W1, b1, W2, b2);
    k_final<<<1, 32>>>(out);
}

// round 5
// speedup vs baseline: 1.1204x; 1.1204x over previous
#include <cuda_runtime.h>
#include <math.h>

#define C_ 10
#define Q_ 1000
#define R_ 1024
#define N_ 512
#define S_ 10000
#define CQ 10000
#define SPLITK 8

// ---------------- static device scratch ----------------
__device__ float g_X[CQ * R_];                         // centered data (40MB)
__device__ float g_Spart[SPLITK * 36 * 128 * 128];     // gram partials (18.9MB)
__device__ float g_S[R_ * R_];                         // sigma -> L in lower tri
__device__ float g_mu[C_ * R_];
__device__ float g_scores[N_ * C_];
__device__ float g_svos[C_ * C_];
__device__ float g_vos[C_ * R_];
__device__ int   g_list[C_ * N_];
__device__ int   g_kc[C_];
__device__ unsigned long long g_amax[C_];
__device__ float g_cls_part[N_];
__device__ float g_bce[N_ + C_];

// ---------------- helpers ----------------
__device__ __forceinline__ unsigned long long dup2(float a) {
    unsigned long long r; asm("mov.b64 %0, {%1, %1};" : "=l"(r) : "f"(a)); return r;
}
__device__ __forceinline__ void fma2(unsigned long long& d, unsigned long long a, unsigned long long b) {
    asm("fma.rn.f32x2 %0, %1, %2, %0;" : "+l"(d) : "l"(a), "l"(b));
}
union F4U { float4 f4; unsigned long long u[2]; float f[4]; };

__device__ __forceinline__ void tri_decode(int t, int& i, int& j) {
    int ti = (int)((sqrtf(8.f * (float)t + 1.f) - 1.f) * 0.5f);
    while ((ti + 1) * (ti + 2) / 2 <= t) ti++;
    while (ti * (ti + 1) / 2 > t) ti--;
    i = ti; j = t - ti * (ti + 1) / 2;
}

// ---------------- per-class ordered sample lists + amax reset ----------------
__global__ void k_lists(const int* __restrict__ labels) {
    __shared__ int lab[N_];
    int tid = threadIdx.x;
    if (tid < N_) lab[tid] = labels[tid];
    __syncthreads();
    if (tid < C_) {
        g_amax[tid] = 0ull;
        int k = 0;
        for (int n = 0; n < N_; n++) if (lab[n] == tid) g_list[tid * N_ + (k++)] = n;
        g_kc[tid] = k;
    }
}

// ---------------- scores + focal loss ----------------
__global__ void k_scores_cls(const float* __restrict__ box, const float* __restrict__ Wp,
                             const float* __restrict__ bp, const int* __restrict__ labels) {
    int n = blockIdx.x; int wid = threadIdx.x >> 5; int lane = threadIdx.x & 31;
    __shared__ float terms[C_];
    const float4* f = (const float4*)(box + (size_t)n * R_);
    const float4* w = (const float4*)(Wp + (size_t)wid * R_);
    float s = 0.f;
#pragma unroll
    for (int i = 0; i < 8; i++) {
        float4 a = f[lane + i * 32]; float4 b = w[lane + i * 32];
        s += a.x * b.x + a.y * b.y + a.z * b.z + a.w * b.w;
    }
    for (int o = 16; o; o >>= 1) s += __shfl_xor_sync(0xffffffffu, s, o);
    if (lane == 0) {
        float sc = s + bp[wid];
        g_scores[n * C_ + wid] = sc;
        float t = (labels[n] == wid) ? 1.f : 0.f;
        float ce = fmaxf(sc, 0.f) - sc * t + log1pf(expf(-fabsf(sc)));
        float p = 1.f / (1.f + expf(-sc));
        float pt = p * t + (1.f - p) * (1.f - t);
        float at = 0.25f * t + 0.75f * (1.f - t);
        float om = 1.f - pt;
        terms[wid] = at * ce * om * om;
    }
    __syncthreads();
    if (threadIdx.x == 0) {
        float acc = 0.f;
#pragma unroll
        for (int c = 0; c < C_; c++) acc += terms[c];
        g_cls_part[n] = acc;
    }
}

// ---------------- per-class mean of post-update queue ----------------
__global__ void k_mu(const float* __restrict__ idd, const float* __restrict__ box) {
    int c = blockIdx.x; int r = blockIdx.y * 128 + threadIdx.x;
    int kc = g_kc[c];
    float s = 0.f;
    const float* base = idd + (size_t)c * Q_ * R_ + r;
    for (int q = kc; q < Q_; q++) s += base[(size_t)q * R_];
    for (int i = 0; i < kc; i++) s += box[(size_t)g_list[c * N_ + i] * R_ + r];
    g_mu[c * R_ + r] = s * (1.f / (float)Q_);
}

// ---------------- centered X ----------------
__global__ void k_buildX(const float* __restrict__ idd, const float* __restrict__ box) {
    int k = blockIdx.x;
    int c = k / Q_; int q = k - c * Q_;
    int kc = g_kc[c]; int q2 = q + kc;
    const float4* src;
    if (q2 < Q_) src = (const float4*)(idd + ((size_t)c * Q_ + q2) * R_);
    else         src = (const float4*)(box + (size_t)g_list[c * N_ + (q2 - Q_)] * R_);
    const float4* mu = (const float4*)(g_mu + c * R_);
    float4 v = src[threadIdx.x]; float4 m = mu[threadIdx.x];
    v.x -= m.x; v.y -= m.y; v.z -= m.z; v.w -= m.w;
    ((float4*)(g_X + (size_t)k * R_))[threadIdx.x] = v;
}

// ---------------- Gram X^T X: lower-tri 128x128 tiles, split-K=8 uneven, f32x2 ----------------
__global__ void __launch_bounds__(256) k_gram() {
    __shared__ float As[8][128], Bs[8][128];
    int t36 = blockIdx.x, kz = blockIdx.y;
    int ti, tj; tri_decode(t36, ti, tj);
    int tid = threadIdx.x;
    int kr = tid >> 5, cf = tid & 31;
    int tx = tid & 15, ty = tid >> 4;
    unsigned long long acc[8][4];
#pragma unroll
    for (int i = 0; i < 8; i++)
#pragma unroll
        for (int j = 0; j < 4; j++) acc[i][j] = 0ull;
    int k0 = kz * 1248;
    int klen = (kz == SPLITK - 1) ? 1264 : 1248;
    const float* XA = g_X + (size_t)ti * 128;
    const float* XB = g_X + (size_t)tj * 128;
    for (int kb = 0; kb < klen; kb += 8) {
        size_t krow = (size_t)(k0 + kb + kr) * R_;
        *(float4*)&As[kr][cf * 4] = *(const float4*)&XA[krow + cf * 4];
        *(float4*)&Bs[kr][cf * 4] = *(const float4*)&XB[krow + cf * 4];
        __syncthreads();
#pragma unroll
        for (int kk = 0; kk < 8; kk++) {
            F4U a0, a1, b0, b1;
            a0.f4 = *(float4*)&As[kk][ty * 8];
            a1.f4 = *(float4*)&As[kk][ty * 8 + 4];
            b0.f4 = *(float4*)&Bs[kk][tx * 8];
            b1.f4 = *(float4*)&Bs[kk][tx * 8 + 4];
            unsigned long long bu[4] = { b0.u[0], b0.u[1], b1.u[0], b1.u[1] };
#pragma unroll
            for (int i = 0; i < 4; i++) {
                unsigned long long ad0 = dup2(a0.f[i]);
                unsigned long long ad1 = dup2(a1.f[i]);
#pragma unroll
                for (int j = 0; j < 4; j++) {
                    fma2(acc[i][j], ad0, bu[j]);
                    fma2(acc[i + 4][j], ad1, bu[j]);
                }
            }
        }
        __syncthreads();
    }
    float* outp = g_Spart + (size_t)(kz * 36 + t36) * 16384;
#pragma unroll
    for (int i = 0; i < 8; i++)
#pragma unroll
        for (int j = 0; j < 4; j++) {
            unsigned long long v = acc[i][j];
            float lo = __uint_as_float((unsigned)(v & 0xffffffffull));
            float hi = __uint_as_float((unsigned)(v >> 32));
            outp[(ty * 8 + i) * 128 + tx * 8 + 2 * j] = lo;
            outp[(ty * 8 + i) * 128 + tx * 8 + 2 * j + 1] = hi;
        }
}

// ---------------- reduce partials -> sigma (symmetric, +eps I) ----------------
__global__ void k_gram_reduce() {
    int t36 = blockIdx.x;
    int ti, tj; tri_decode(t36, ti, tj);
    for (int e = 0; e < 64; e++) {
        int idx = e * 256 + threadIdx.x;
        int r = idx >> 7, c = idx & 127;
        float s = 0.f;
#pragma unroll
        for (int kz = 0; kz < SPLITK; kz++)
            s += g_Spart[(size_t)(kz * 36 + t36) * 16384 + idx];
        float val = s / 10000.f;
        int gi = ti * 128 + r, gj = tj * 128 + c;
        if (gi == gj) val += 1e-4f;
        g_S[(size_t)gi * R_ + gj] = val;
        g_S[(size_t)gj * R_ + gi] = val;
    }
}

// ---------------- Cholesky diag panel: LDL-style, 1 barrier per column ----------------
__global__ void k_chol_diag(int p) {
    __shared__ float T[128 * 129 / 2];
    int base = p * 128;
    int tid = threadIdx.x;              // 512 threads
    int x = tid & 127, y = tid >> 7;    // y in 0..3
    for (int i = y; i < 128; i += 4)
        if (x <= i) T[i * (i + 1) / 2 + x] = g_S[(size_t)(base + i) * R_ + base + x];
    __syncthreads();
    for (int j = 0; j < 128; j++) {
        float dj = T[j * (j + 1) / 2 + j];
        float inv = __fdividef(1.f, dj);
        if (x > j) {
            float lxj = T[x * (x + 1) / 2 + j] * inv;
            for (int k = j + 1 + y; k <= x; k += 4)
                T[x * (x + 1) / 2 + k] -= lxj * T[k * (k + 1) / 2 + j];
        }
        __syncthreads();
    }
    for (int i = y; i < 128; i += 4)
        if (x <= i) {
            float d = T[x * (x + 1) / 2 + x];
            g_S[(size_t)(base + i) * R_ + base + x] = T[i * (i + 1) / 2 + x] * rsqrtf(d);
        }
}

// ---------------- trsm: smem-staged L11^T, barrier-free solve loop ----------------
__global__ void k_trsm(int p) {
    __shared__ float U[8256];     // packed: U[off(j)+(k-j)] = L[k][j], off(j)=j*128-j*(j-1)/2
    __shared__ float dinv[128];
    int base = p * 128;
    int tid = threadIdx.x;        // 256 threads
    int w = tid >> 5, lane = tid & 31;
    for (int k = w; k < 128; k += 8) {
        for (int j = lane; j <= k; j += 32) {
            int offj = j * 128 - (j * (j - 1)) / 2;
            U[offj + (k - j)] = g_S[(size_t)(base + k) * R_ + base + j];
        }
    }
    __syncthreads();
    if (tid < 128) {
        int offj = tid * 128 - (tid * (tid - 1)) / 2;
        dinv[tid] = __fdividef(1.f, U[offj]);
    }
    __syncthreads();
    int row = base + 128 + blockIdx.x * 8 + w;
    float* arow = g_S + (size_t)row * R_ + base;
    float a0 = arow[lane], a1 = arow[lane + 32], a2 = arow[lane + 64], a3 = arow[lane + 96];
    int offj = 0;
    for (int j = 0; j < 128; j++) {
        int src = j & 31, slot = j >> 5;
        float aval = (slot == 0) ? a0 : (slot == 1) ? a1 : (slot == 2) ? a2 : a3;
        float xj = __shfl_sync(0xffffffffu, aval, src) * dinv[j];
        if (lane == src) {
            if (slot == 0) a0 = xj; else if (slot == 1) a1 = xj;
            else if (slot == 2) a2 = xj; else a3 = xj;
        }
        if (lane > j)      a0 -= xj * U[offj + (lane - j)];
        if (lane + 32 > j) a1 -= xj * U[offj + (lane + 32 - j)];
        if (lane + 64 > j) a2 -= xj * U[offj + (lane + 64 - j)];
        if (lane + 96 > j) a3 -= xj * U[offj + (lane + 96 - j)];
        offj += 128 - j;
    }
    arow[lane] = a0; arow[lane + 32] = a1; arow[lane + 64] = a2; arow[lane + 96] = a3;
}

// ---------------- syrk trailing update (64x64 tiles) ----------------
__global__ void k_syrk(int p) {
    __shared__ float As[64][17], Bs[64][17];
    int base = p * 128, trail = base + 128;
    int ti, tj; tri_decode(blockIdx.x, ti, tj);
    int gi0 = trail + ti * 64, gj0 = trail + tj * 64;
    int tid = threadIdx.x;
    int tx = tid & 15, ty = tid >> 4;
    float acc[4][4];
#pragma unroll
    for (int r = 0; r < 4; r++)
#pragma unroll
        for (int s = 0; s < 4; s++) acc[r][s] = 0.f;
    for (int kc = 0; kc < 128; kc += 16) {
        int li = tid >> 2, lk = (tid & 3) * 4;
        float4 va = *(const float4*)&g_S[(size_t)(gi0 + li) * R_ + base + kc + lk];
        float4 vb = *(const float4*)&g_S[(size_t)(gj0 + li) * R_ + base + kc + lk];
        As[li][lk] = va.x; As[li][lk + 1] = va.y; As[li][lk + 2] = va.z; As[li][lk + 3] = va.w;
        Bs[li][lk] = vb.x; Bs[li][lk + 1] = vb.y; Bs[li][lk + 2] = vb.z; Bs[li][lk + 3] = vb.w;
        __syncthreads();
#pragma unroll
        for (int kk = 0; kk < 16; kk++) {
            float a[4], b[4];
#pragma unroll
            for (int r = 0; r < 4; r++) a[r] = As[ty * 4 + r][kk];
#pragma unroll
            for (int s = 0; s < 4; s++) b[s] = Bs[tx * 4 + s][kk];
#pragma unroll
            for (int r = 0; r < 4; r++)
#pragma unroll
                for (int s = 0; s < 4; s++) acc[r][s] += a[r] * b[s];
        }
        __syncthreads();
    }
#pragma unroll
    for (int r = 0; r < 4; r++)
#pragma unroll
        for (int s = 0; s < 4; s++)
            g_S[(size_t)(gi0 + ty * 4 + r) * R_ + gj0 + tx * 4 + s] -= acc[r][s];
}

// ---------------- eps argmax of ||eps[c,s]||^2 (warp per row) ----------------
__global__ void k_eps(const float* __restrict__ eps) {
    int w = blockIdx.x * 8 + (threadIdx.x >> 5);
    int lane = threadIdx.x & 31;
    int c = w / S_, s = w - c * S_;
    const float4* row = (const float4*)(eps + (size_t)w * R_);
    float acc = 0.f;
#pragma unroll
    for (int i = 0; i < 8; i++) {
        float4 v = row[lane + i * 32];
        acc += v.x * v.x + v.y * v.y + v.z * v.z + v.w * v.w;
    }
    for (int o = 16; o; o >>= 1) acc += __shfl_xor_sync(0xffffffffu, acc, o);
    if (lane == 0) {
        unsigned long long key = ((unsigned long long)__float_as_uint(acc) << 32)
                               | (unsigned long long)(0x7FFFFFFFu - (unsigned)s);
        atomicMax(&g_amax[c], key);
    }
}

// ---------------- vos = mu + L @ eps_sel (warp per output element) ----------------
__global__ void k_vos(const float* __restrict__ eps) {
    int c = blockIdx.y;
    int r = blockIdx.x * 8 + (threadIdx.x >> 5);
    int lane = threadIdx.x & 31;
    int idx = 0x7FFFFFFF - (int)(unsigned)(g_amax[c] & 0xffffffffull);
    const float* erow = eps + ((size_t)c * S_ + idx) * R_;
    const float* Lr = g_S + (size_t)r * R_;
    float s = 0.f;
    for (int j = lane; j <= r; j += 32) s += erow[j] * Lr[j];
    for (int o = 16; o; o >>= 1) s += __shfl_xor_sync(0xffffffffu, s, o);
    if (lane == 0) g_vos[c * R_ + r] = g_mu[c * R_ + r] + s;
}

// ---------------- scores_vos ----------------
__global__ void k_svos(const float* __restrict__ Wp, const float* __restrict__ bp) {
    int i = blockIdx.x, j = blockIdx.y;
    int tid = threadIdx.x;
    __shared__ float ws[4];
    float s = 0.f;
    for (int r = tid; r < R_; r += 128) s += g_vos[i * R_ + r] * Wp[(size_t)j * R_ + r];
    for (int o = 16; o; o >>= 1) s += __shfl_xor_sync(0xffffffffu, s, o);
    if ((tid & 31) == 0) ws[tid >> 5] = s;
    __syncthreads();
    if (tid == 0) g_svos[i * C_ + j] = ws[0] + ws[1] + ws[2] + ws[3] + bp[j];
}

// ---------------- energy + MLP + BCE (warp per item) ----------------
__global__ void k_energy(const float* __restrict__ we, const float* __restrict__ W1,
                         const float* __restrict__ b1, const float* __restrict__ W2,
                         const float* __restrict__ b2) {
    int item = blockIdx.x * 8 + (threadIdx.x >> 5);
    int lane = threadIdx.x & 31;
    if (item >= N_ + C_) return;
    float x = -1e30f;
    if (lane < C_) x = (item < N_) ? g_scores[item * C_ + lane] : g_svos[(item - N_) * C_ + lane];
    float m = x;
    for (int o = 16; o; o >>= 1) m = fmaxf(m, __shfl_xor_sync(0xffffffffu, m, o));
    float t = (lane < C_) ? expf(x - m) * fmaxf(we[lane], 0.f) : 0.f;
    for (int o = 16; o; o >>= 1) t += __shfl_xor_sync(0xffffffffu, t, o);
    float e = m + logf(t);
    float acc = 0.f;
    for (int j = lane; j < 512; j += 32) acc += fmaxf(e * W1[j] + b1[j], 0.f) * W2[j];
    for (int o = 16; o; o >>= 1) acc += __shfl_xor_sync(0xffffffffu, acc, o);
    if (lane == 0) {
        float l = acc + b2[0];
        float y = (item < N_) ? 1.f : 0.f;
        g_bce[item] = fmaxf(l, 0.f) - l * y + log1pf(expf(-fabsf(l)));
    }
}

// ---------------- final reduction (parallel; folds the 10 tail items) ----------------
__global__ void k_final(float* __restrict__ out) {
    __shared__ float sc[16], sd[16];
    int tid = threadIdx.x;               // 512
    int w = tid >> 5, lane = tid & 31;
    float a = g_cls_part[tid];
    float b = g_bce[tid] + ((tid < C_) ? g_bce[N_ + tid] : 0.f);
    for (int o = 16; o; o >>= 1) { a += __shfl_xor_sync(0xffffffffu, a, o); b += __shfl_xor_sync(0xffffffffu, b, o); }
    if (lane == 0) { sc[w] = a; sd[w] = b; }
    __syncthreads();
    if (tid == 0) {
        float cs = 0.f, ds = 0.f;
#pragma unroll
        for (int i = 0; i < 16; i++) { cs += sc[i]; ds += sd[i]; }
        out[0] = cs / (float)N_;
        out[1] = 0.1f * ds / (float)(N_ + C_);
    }
}

extern "C" void kernel_launch(void* const* d_in, const int* in_sizes, int n_in,
                              void* d_out, int out_size) {
    const float* box = (const float*)d_in[0];
    const int* labels = (const int*)d_in[1];
    const float* idd = (const float*)d_in[2];
    const float* Wp = (const float*)d_in[4];
    const float* bp = (const float*)d_in[5];
    const float* we = (const float*)d_in[6];
    const float* W1 = (const float*)d_in[7];
    const float* b1 = (const float*)d_in[8];
    const float* W2 = (const float*)d_in[9];
    const float* b2 = (const float*)d_in[10];
    const float* eps = (const float*)d_in[11];
    float* out = (float*)d_out;

    k_lists<<<1, 512>>>(labels);
    k_scores_cls<<<N_, 320>>>(box, Wp, bp, labels);
    k_mu<<<dim3(C_, 8), 128>>>(idd, box);
    k_buildX<<<CQ, 256>>>(idd, box);
    k_gram<<<dim3(36, SPLITK), 256>>>();
    k_gram_reduce<<<36, 256>>>();
    for (int p = 0; p < 8; p++) {
        k_chol_diag<<<1, 512>>>(p);
        int nrows = R_ - (p + 1) * 128;
        if (nrows > 0) {
            k_trsm<<<nrows / 8, 256>>>(p);
            int T = nrows / 64;
            k_syrk<<<T * (T + 1) / 2, 256>>>(p);
        }
    }
    k_eps<<<(C_ * S_) / 8, 256>>>(eps);
    k_vos<<<dim3(128, C_), 256>>>(eps);
    k_svos<<<dim3(C_, C_), 128>>>(Wp, bp);
    k_energy<<<(N_ + C_ + 7) / 8, 256>>>(we, W1, b1, W2, b2);
    k_final<<<1, 512>>>(out);
}

// round 7
// speedup vs baseline: 1.3136x; 1.1724x over previous
#include <cuda_runtime.h>
#include <math.h>

#define C_ 10
#define Q_ 1000
#define R_ 1024
#define N_ 512
#define S_ 10000
#define CQ 10000
#define SPLITK 8

// ---------------- static device scratch ----------------
__device__ float g_X[CQ * R_];                         // centered data (40MB)
__device__ float g_Spart[SPLITK * 36 * 128 * 128];     // gram partials (18.9MB)
__device__ float g_S[R_ * R_];                         // sigma -> L in lower tri
__device__ float g_mu[C_ * R_];
__device__ float g_mupart[C_ * 8 * R_];
__device__ float g_scores[N_ * C_];
__device__ float g_svos[C_ * C_];
__device__ float g_vos[C_ * R_];
__device__ int   g_list[C_ * N_];
__device__ int   g_kc[C_];
__device__ unsigned long long g_amax[C_];
__device__ float g_cls_part[N_];
__device__ float g_bce[N_ + C_];

// ---------------- helpers ----------------
__device__ __forceinline__ unsigned long long dup2(float a) {
    unsigned long long r; asm("mov.b64 %0, {%1, %1};" : "=l"(r) : "f"(a)); return r;
}
__device__ __forceinline__ void fma2(unsigned long long& d, unsigned long long a, unsigned long long b) {
    asm("fma.rn.f32x2 %0, %1, %2, %0;" : "+l"(d) : "l"(a), "l"(b));
}
union F4U { float4 f4; unsigned long long u[2]; float f[4]; };

__device__ __forceinline__ void tri_decode(int t, int& i, int& j) {
    int ti = (int)((sqrtf(8.f * (float)t + 1.f) - 1.f) * 0.5f);
    while ((ti + 1) * (ti + 2) / 2 <= t) ti++;
    while (ti * (ti + 1) / 2 > t) ti--;
    i = ti; j = t - ti * (ti + 1) / 2;
}

// ---------------- per-class ordered sample lists + amax reset ----------------
__global__ void k_lists(const int* __restrict__ labels) {
    __shared__ int lab[N_];
    int tid = threadIdx.x;
    if (tid < N_) lab[tid] = labels[tid];
    __syncthreads();
    if (tid < C_) {
        g_amax[tid] = 0ull;
        int k = 0;
        for (int n = 0; n < N_; n++) if (lab[n] == tid) g_list[tid * N_ + (k++)] = n;
        g_kc[tid] = k;
    }
}

// ---------------- scores + focal loss ----------------
__global__ void k_scores_cls(const float* __restrict__ box, const float* __restrict__ Wp,
                             const float* __restrict__ bp, const int* __restrict__ labels) {
    int n = blockIdx.x; int wid = threadIdx.x >> 5; int lane = threadIdx.x & 31;
    __shared__ float terms[C_];
    const float4* f = (const float4*)(box + (size_t)n * R_);
    const float4* w = (const float4*)(Wp + (size_t)wid * R_);
    float s = 0.f;
#pragma unroll
    for (int i = 0; i < 8; i++) {
        float4 a = f[lane + i * 32]; float4 b = w[lane + i * 32];
        s += a.x * b.x + a.y * b.y + a.z * b.z + a.w * b.w;
    }
    for (int o = 16; o; o >>= 1) s += __shfl_xor_sync(0xffffffffu, s, o);
    if (lane == 0) {
        float sc = s + bp[wid];
        g_scores[n * C_ + wid] = sc;
        float t = (labels[n] == wid) ? 1.f : 0.f;
        float ce = fmaxf(sc, 0.f) - sc * t + log1pf(expf(-fabsf(sc)));
        float p = 1.f / (1.f + expf(-sc));
        float pt = p * t + (1.f - p) * (1.f - t);
        float at = 0.25f * t + 0.75f * (1.f - t);
        float om = 1.f - pt;
        terms[wid] = at * ce * om * om;
    }
    __syncthreads();
    if (threadIdx.x == 0) {
        float acc = 0.f;
#pragma unroll
        for (int c = 0; c < C_; c++) acc += terms[c];
        g_cls_part[n] = acc;
    }
}

// ---------------- per-class mean, stage 1: q-chunk partial sums ----------------
__global__ void k_mu_part(const float* __restrict__ idd, const float* __restrict__ box) {
    int c = blockIdx.x, chunk = blockIdx.y;
    int r = threadIdx.x;                  // 1024
    int kc = g_kc[c];
    int nold = Q_ - kc;
    float s = 0.f;
#pragma unroll 5
    for (int q2 = chunk * 125; q2 < (chunk + 1) * 125; q2++) {
        if (q2 < nold) s += idd[((size_t)c * Q_ + kc + q2) * R_ + r];
        else           s += box[(size_t)g_list[c * N_ + (q2 - nold)] * R_ + r];
    }
    g_mupart[(c * 8 + chunk) * R_ + r] = s;
}

// ---------------- per-class mean, stage 2 ----------------
__global__ void k_mu_fin() {
    int c = blockIdx.x; int r = threadIdx.x;
    float s = 0.f;
#pragma unroll
    for (int k = 0; k < 8; k++) s += g_mupart[(c * 8 + k) * R_ + r];
    g_mu[c * R_ + r] = s * (1.f / (float)Q_);
}

// ---------------- centered X ----------------
__global__ void k_buildX(const float* __restrict__ idd, const float* __restrict__ box) {
    int k = blockIdx.x;
    int c = k / Q_; int q = k - c * Q_;
    int kc = g_kc[c]; int q2 = q + kc;
    const float4* src;
    if (q2 < Q_) src = (const float4*)(idd + ((size_t)c * Q_ + q2) * R_);
    else         src = (const float4*)(box + (size_t)g_list[c * N_ + (q2 - Q_)] * R_);
    const float4* mu = (const float4*)(g_mu + c * R_);
    float4 v = src[threadIdx.x]; float4 m = mu[threadIdx.x];
    v.x -= m.x; v.y -= m.y; v.z -= m.z; v.w -= m.w;
    ((float4*)(g_X + (size_t)k * R_))[threadIdx.x] = v;
}

// ---------------- Gram X^T X: 128x128 lower-tri tiles, split-K, f32x2, reg-prefetch pipeline ----------------
__global__ void __launch_bounds__(256, 2) k_gram() {
    __shared__ float As[8][128], Bs[8][128];
    int t36 = blockIdx.x, kz = blockIdx.y;
    int ti, tj; tri_decode(t36, ti, tj);
    int tid = threadIdx.x;
    int kr = tid >> 5, cf = tid & 31;
    int tx = tid & 15, ty = tid >> 4;
    unsigned long long acc[8][4];
#pragma unroll
    for (int i = 0; i < 8; i++)
#pragma unroll
        for (int j = 0; j < 4; j++) acc[i][j] = 0ull;
    int k0 = kz * 1248;
    int klen = (kz == SPLITK - 1) ? 1264 : 1248;
    const float* XA = g_X + (size_t)ti * 128 + (size_t)(k0 + kr) * R_ + cf * 4;
    const float* XB = g_X + (size_t)tj * 128 + (size_t)(k0 + kr) * R_ + cf * 4;
    float4 ra = *(const float4*)XA;
    float4 rb = *(const float4*)XB;
    for (int kb = 0; kb < klen; kb += 8) {
        *(float4*)&As[kr][cf * 4] = ra;
        *(float4*)&Bs[kr][cf * 4] = rb;
        __syncthreads();
        XA += 8 * R_; XB += 8 * R_;
        if (kb + 8 < klen) { ra = *(const float4*)XA; rb = *(const float4*)XB; }
#pragma unroll
        for (int kk = 0; kk < 8; kk++) {
            F4U a0, a1, b0, b1;
            a0.f4 = *(float4*)&As[kk][ty * 8];
            a1.f4 = *(float4*)&As[kk][ty * 8 + 4];
            b0.f4 = *(float4*)&Bs[kk][tx * 8];
            b1.f4 = *(float4*)&Bs[kk][tx * 8 + 4];
            unsigned long long bu[4] = { b0.u[0], b0.u[1], b1.u[0], b1.u[1] };
#pragma unroll
            for (int i = 0; i < 4; i++) {
                unsigned long long ad0 = dup2(a0.f[i]);
                unsigned long long ad1 = dup2(a1.f[i]);
#pragma unroll
                for (int j = 0; j < 4; j++) {
                    fma2(acc[i][j], ad0, bu[j]);
                    fma2(acc[i + 4][j], ad1, bu[j]);
                }
            }
        }
        __syncthreads();
    }
    float* outp = g_Spart + (size_t)(kz * 36 + t36) * 16384;
#pragma unroll
    for (int i = 0; i < 8; i++)
#pragma unroll
        for (int j = 0; j < 4; j++) {
            unsigned long long v = acc[i][j];
            float lo = __uint_as_float((unsigned)(v & 0xffffffffull));
            float hi = __uint_as_float((unsigned)(v >> 32));
            outp[(ty * 8 + i) * 128 + tx * 8 + 2 * j] = lo;
            outp[(ty * 8 + i) * 128 + tx * 8 + 2 * j + 1] = hi;
        }
}

// ---------------- reduce partials -> sigma (symmetric, +eps I) ----------------
__global__ void k_gram_reduce() {
    int t36 = blockIdx.x;
    int ti, tj; tri_decode(t36, ti, tj);
    for (int e = 0; e < 64; e++) {
        int idx = e * 256 + threadIdx.x;
        int r = idx >> 7, c = idx & 127;
        float s = 0.f;
#pragma unroll
        for (int kz = 0; kz < SPLITK; kz++)
            s += g_Spart[(size_t)(kz * 36 + t36) * 16384 + idx];
        float val = s / 10000.f;
        int gi = ti * 128 + r, gj = tj * 128 + c;
        if (gi == gj) val += 1e-4f;
        g_S[(size_t)gi * R_ + gj] = val;
        g_S[(size_t)gj * R_ + gi] = val;
    }
}

// ---------------- Cholesky diag panel: column-major smem (stride 129), conflict-free ----------------
// Tc[col*129 + row] holds working element (row, col), col <= row (lower triangle).
__global__ void k_chol_diag(int p) {
    extern __shared__ float Tc[];       // 128*129 floats = 66048 B
    int base = p * 128;
    int tid = threadIdx.x;              // 512 threads
    int x = tid & 127, y = tid >> 7;    // y in 0..3
    // load: thread x owns column x; rows i >= x. Coalesced gmem reads, conflict-free smem.
    for (int i = y; i < 128; i += 4)
        if (x <= i) Tc[x * 129 + i] = g_S[(size_t)(base + i) * R_ + base + x];
    __syncthreads();
    for (int j = 0; j < 128; j++) {
        float inv = __fdividef(1.f, Tc[j * 129 + j]);
        if (x > j) {
            float lxj = Tc[j * 129 + x] * inv;     // element (x, j)
            for (int k = j + 1 + y; k <= x; k += 4)
                Tc[k * 129 + x] -= lxj * Tc[j * 129 + k];   // (x,k) -= lxj * (k,j)
        }
        __syncthreads();
    }
    // scale: L[i][x] = A[i][x] * rsqrt(d_x); write coalesced by row i
    for (int i = y; i < 128; i += 4)
        if (x <= i)
            g_S[(size_t)(base + i) * R_ + base + x] = Tc[x * 129 + i] * rsqrtf(Tc[x * 129 + x]);
}

// ---------------- trsm: smem-staged L11^T, barrier-free solve loop ----------------
__global__ void k_trsm(int p) {
    __shared__ float U[8256];     // packed: U[off(j)+(k-j)] = L[k][j], off(j)=j*128-j*(j-1)/2
    __shared__ float dinv[128];
    int base = p * 128;
    int tid = threadIdx.x;        // 256 threads
    int w = tid >> 5, lane = tid & 31;
    for (int k = w; k < 128; k += 8) {
        for (int j = lane; j <= k; j += 32) {
            int offj = j * 128 - (j * (j - 1)) / 2;
            U[offj + (k - j)] = g_S[(size_t)(base + k) * R_ + base + j];
        }
    }
    __syncthreads();
    if (tid < 128) {
        int offj = tid * 128 - (tid * (tid - 1)) / 2;
        dinv[tid] = __fdividef(1.f, U[offj]);
    }
    __syncthreads();
    int row = base + 128 + blockIdx.x * 8 + w;
    float* arow = g_S + (size_t)row * R_ + base;
    float a0 = arow[lane], a1 = arow[lane + 32], a2 = arow[lane + 64], a3 = arow[lane + 96];
    int offj = 0;
    for (int j = 0; j < 128; j++) {
        int src = j & 31, slot = j >> 5;
        float aval = (slot == 0) ? a0 : (slot == 1) ? a1 : (slot == 2) ? a2 : a3;
        float xj = __shfl_sync(0xffffffffu, aval, src) * dinv[j];
        if (lane == src) {
            if (slot == 0) a0 = xj; else if (slot == 1) a1 = xj;
            else if (slot == 2) a2 = xj; else a3 = xj;
        }
        if (lane > j)      a0 -= xj * U[offj + (lane - j)];
        if (lane + 32 > j) a1 -= xj * U[offj + (lane + 32 - j)];
        if (lane + 64 > j) a2 -= xj * U[offj + (lane + 64 - j)];
        if (lane + 96 > j) a3 -= xj * U[offj + (lane + 96 - j)];
        offj += 128 - j;
    }
    arow[lane] = a0; arow[lane + 32] = a1; arow[lane + 64] = a2; arow[lane + 96] = a3;
}

// ---------------- syrk trailing update (64x64 tiles) ----------------
__global__ void k_syrk(int p) {
    __shared__ float As[64][17], Bs[64][17];
    int base = p * 128, trail = base + 128;
    int ti, tj; tri_decode(blockIdx.x, ti, tj);
    int gi0 = trail + ti * 64, gj0 = trail + tj * 64;
    int tid = threadIdx.x;
    int tx = tid & 15, ty = tid >> 4;
    float acc[4][4];
#pragma unroll
    for (int r = 0; r < 4; r++)
#pragma unroll
        for (int s = 0; s < 4; s++) acc[r][s] = 0.f;
    for (int kc = 0; kc < 128; kc += 16) {
        int li = tid >> 2, lk = (tid & 3) * 4;
        float4 va = *(const float4*)&g_S[(size_t)(gi0 + li) * R_ + base + kc + lk];
        float4 vb = *(const float4*)&g_S[(size_t)(gj0 + li) * R_ + base + kc + lk];
        As[li][lk] = va.x; As[li][lk + 1] = va.y; As[li][lk + 2] = va.z; As[li][lk + 3] = va.w;
        Bs[li][lk] = vb.x; Bs[li][lk + 1] = vb.y; Bs[li][lk + 2] = vb.z; Bs[li][lk + 3] = vb.w;
        __syncthreads();
#pragma unroll
        for (int kk = 0; kk < 16; kk++) {
            float a[4], b[4];
#pragma unroll
            for (int r = 0; r < 4; r++) a[r] = As[ty * 4 + r][kk];
#pragma unroll
            for (int s = 0; s < 4; s++) b[s] = Bs[tx * 4 + s][kk];
#pragma unroll
            for (int r = 0; r < 4; r++)
#pragma unroll
                for (int s = 0; s < 4; s++) acc[r][s] += a[r] * b[s];
        }
        __syncthreads();
    }
#pragma unroll
    for (int r = 0; r < 4; r++)
#pragma unroll
        for (int s = 0; s < 4; s++)
            g_S[(size_t)(gi0 + ty * 4 + r) * R_ + gj0 + tx * 4 + s] -= acc[r][s];
}

// ---------------- eps argmax of ||eps[c,s]||^2 (warp per row, streaming loads) ----------------
__global__ void k_eps(const float* __restrict__ eps) {
    int w = blockIdx.x * 8 + (threadIdx.x >> 5);
    int lane = threadIdx.x & 31;
    int c = w / S_, s = w - c * S_;
    const float4* row = (const float4*)(eps + (size_t)w * R_);
    float acc = 0.f;
#pragma unroll
    for (int i = 0; i < 8; i++) {
        float4 v = __ldcs(&row[lane + i * 32]);
        acc += v.x * v.x + v.y * v.y + v.z * v.z + v.w * v.w;
    }
    for (int o = 16; o; o >>= 1) acc += __shfl_xor_sync(0xffffffffu, acc, o);
    if (lane == 0) {
        unsigned long long key = ((unsigned long long)__float_as_uint(acc) << 32)
                               | (unsigned long long)(0x7FFFFFFFu - (unsigned)s);
        atomicMax(&g_amax[c], key);
    }
}

// ---------------- vos = mu + L @ eps_sel (warp per output element) ----------------
__global__ void k_vos(const float* __restrict__ eps) {
    int c = blockIdx.y;
    int r = blockIdx.x * 8 + (threadIdx.x >> 5);
    int lane = threadIdx.x & 31;
    int idx = 0x7FFFFFFF - (int)(unsigned)(g_amax[c] & 0xffffffffull);
    const float* erow = eps + ((size_t)c * S_ + idx) * R_;
    const float* Lr = g_S + (size_t)r * R_;
    float s = 0.f;
    for (int j = lane; j <= r; j += 32) s += erow[j] * Lr[j];
    for (int o = 16; o; o >>= 1) s += __shfl_xor_sync(0xffffffffu, s, o);
    if (lane == 0) g_vos[c * R_ + r] = g_mu[c * R_ + r] + s;
}

// ---------------- scores_vos ----------------
__global__ void k_svos(const float* __restrict__ Wp, const float* __restrict__ bp) {
    int i = blockIdx.x, j = blockIdx.y;
    int tid = threadIdx.x;
    __shared__ float ws[4];
    float s = 0.f;
    for (int r = tid; r < R_; r += 128) s += g_vos[i * R_ + r] * Wp[(size_t)j * R_ + r];
    for (int o = 16; o; o >>= 1) s += __shfl_xor_sync(0xffffffffu, s, o);
    if ((tid & 31) == 0) ws[tid >> 5] = s;
    __syncthreads();
    if (tid == 0) g_svos[i * C_ + j] = ws[0] + ws[1] + ws[2] + ws[3] + bp[j];
}

// ---------------- energy + MLP + BCE (warp per item) ----------------
__global__ void k_energy(const float* __restrict__ we, const float* __restrict__ W1,
                         const float* __restrict__ b1, const float* __restrict__ W2,
                         const float* __restrict__ b2) {
    int item = blockIdx.x * 8 + (threadIdx.x >> 5);
    int lane = threadIdx.x & 31;
    if (item >= N_ + C_) return;
    float x = -1e30f;
    if (lane < C_) x = (item < N_) ? g_scores[item * C_ + lane] : g_svos[(item - N_) * C_ + lane];
    float m = x;
    for (int o = 16; o; o >>= 1) m = fmaxf(m, __shfl_xor_sync(0xffffffffu, m, o));
    float t = (lane < C_) ? expf(x - m) * fmaxf(we[lane], 0.f) : 0.f;
    for (int o = 16; o; o >>= 1) t += __shfl_xor_sync(0xffffffffu, t, o);
    float e = m + logf(t);
    float acc = 0.f;
    for (int j = lane; j < 512; j += 32) acc += fmaxf(e * W1[j] + b1[j], 0.f) * W2[j];
    for (int o = 16; o; o >>= 1) acc += __shfl_xor_sync(0xffffffffu, acc, o);
    if (lane == 0) {
        float l = acc + b2[0];
        float y = (item < N_) ? 1.f : 0.f;
        g_bce[item] = fmaxf(l, 0.f) - l * y + log1pf(expf(-fabsf(l)));
    }
}

// ---------------- final reduction (parallel; folds the 10 tail items) ----------------
__global__ void k_final(float* __restrict__ out) {
    __shared__ float sc[16], sd[16];
    int tid = threadIdx.x;               // 512
    int w = tid >> 5, lane = tid & 31;
    float a = g_cls_part[tid];
    float b = g_bce[tid] + ((tid < C_) ? g_bce[N_ + tid] : 0.f);
    for (int o = 16; o; o >>= 1) { a += __shfl_xor_sync(0xffffffffu, a, o); b += __shfl_xor_sync(0xffffffffu, b, o); }
    if (lane == 0) { sc[w] = a; sd[w] = b; }
    __syncthreads();
    if (tid == 0) {
        float cs = 0.f, ds = 0.f;
#pragma unroll
        for (int i = 0; i < 16; i++) { cs += sc[i]; ds += sd[i]; }
        out[0] = cs / (float)N_;
        out[1] = 0.1f * ds / (float)(N_ + C_);
    }
}

extern "C" void kernel_launch(void* const* d_in, const int* in_sizes, int n_in,
                              void* d_out, int out_size) {
    const float* box = (const float*)d_in[0];
    const int* labels = (const int*)d_in[1];
    const float* idd = (const float*)d_in[2];
    const float* Wp = (const float*)d_in[4];
    const float* bp = (const float*)d_in[5];
    const float* we = (const float*)d_in[6];
    const float* W1 = (const float*)d_in[7];
    const float* b1 = (const float*)d_in[8];
    const float* W2 = (const float*)d_in[9];
    const float* b2 = (const float*)d_in[10];
    const float* eps = (const float*)d_in[11];
    float* out = (float*)d_out;

    cudaFuncSetAttribute(k_chol_diag, cudaFuncAttributeMaxDynamicSharedMemorySize, 128 * 129 * 4);

    k_lists<<<1, 512>>>(labels);
    k_scores_cls<<<N_, 320>>>(box, Wp, bp, labels);
    k_mu_part<<<dim3(C_, 8), 1024>>>(idd, box);
    k_mu_fin<<<C_, 1024>>>();
    k_buildX<<<CQ, 256>>>(idd, box);
    k_gram<<<dim3(36, SPLITK), 256>>>();
    k_gram_reduce<<<36, 256>>>();
    for (int p = 0; p < 8; p++) {
        k_chol_diag<<<1, 512, 128 * 129 * 4>>>(p);
        int nrows = R_ - (p + 1) * 128;
        if (nrows > 0) {
            k_trsm<<<nrows / 8, 256>>>(p);
            int T = nrows / 64;
            k_syrk<<<T * (T + 1) / 2, 256>>>(p);
        }
    }
    k_eps<<<(C_ * S_) / 8, 256>>>(eps);
    k_vos<<<dim3(128, C_), 256>>>(eps);
    k_svos<<<dim3(C_, C_), 128>>>(Wp, bp);
    k_energy<<<(N_ + C_ + 7) / 8, 256>>>(we, W1, b1, W2, b2);
    k_final<<<1, 512>>>(out);
}

// round 8
// speedup vs baseline: 1.3149x; 1.0009x over previous
#include <cuda_runtime.h>
#include <math.h>

#define C_ 10
#define Q_ 1000
#define R_ 1024
#define N_ 512
#define S_ 10000
#define CQ 10000
#define SPLITK 8

// ---------------- static device scratch ----------------
__device__ float g_X[CQ * R_];                         // centered data (40MB)
__device__ float g_Spart[SPLITK * 36 * 128 * 128];     // gram partials (18.9MB)
__device__ float g_S[R_ * R_];                         // sigma -> L in lower tri
__device__ float g_mu[C_ * R_];
__device__ float g_mupart[C_ * 8 * R_];
__device__ float g_scores[N_ * C_];
__device__ float g_svos[C_ * C_];
__device__ float g_vos[C_ * R_];
__device__ int   g_list[C_ * N_];
__device__ int   g_kc[C_];
__device__ unsigned long long g_amax[C_];
__device__ float g_cls_part[N_];
__device__ float g_bce[N_ + C_];

// ---------------- helpers ----------------
__device__ __forceinline__ unsigned long long dup2(float a) {
    unsigned long long r; asm("mov.b64 %0, {%1, %1};" : "=l"(r) : "f"(a)); return r;
}
__device__ __forceinline__ void fma2(unsigned long long& d, unsigned long long a, unsigned long long b) {
    asm("fma.rn.f32x2 %0, %1, %2, %0;" : "+l"(d) : "l"(a), "l"(b));
}
union F4U { float4 f4; unsigned long long u[2]; float f[4]; };

__device__ __forceinline__ void tri_decode(int t, int& i, int& j) {
    int ti = (int)((sqrtf(8.f * (float)t + 1.f) - 1.f) * 0.5f);
    while ((ti + 1) * (ti + 2) / 2 <= t) ti++;
    while (ti * (ti + 1) / 2 > t) ti--;
    i = ti; j = t - ti * (ti + 1) / 2;
}

// ---------------- per-class ordered sample lists + amax reset ----------------
__global__ void k_lists(const int* __restrict__ labels) {
    __shared__ int lab[N_];
    int tid = threadIdx.x;
    if (tid < N_) lab[tid] = labels[tid];
    __syncthreads();
    if (tid < C_) {
        g_amax[tid] = 0ull;
        int k = 0;
        for (int n = 0; n < N_; n++) if (lab[n] == tid) g_list[tid * N_ + (k++)] = n;
        g_kc[tid] = k;
    }
}

// ---------------- scores + focal loss ----------------
__global__ void k_scores_cls(const float* __restrict__ box, const float* __restrict__ Wp,
                             const float* __restrict__ bp, const int* __restrict__ labels) {
    int n = blockIdx.x; int wid = threadIdx.x >> 5; int lane = threadIdx.x & 31;
    __shared__ float terms[C_];
    const float4* f = (const float4*)(box + (size_t)n * R_);
    const float4* w = (const float4*)(Wp + (size_t)wid * R_);
    float s = 0.f;
#pragma unroll
    for (int i = 0; i < 8; i++) {
        float4 a = f[lane + i * 32]; float4 b = w[lane + i * 32];
        s += a.x * b.x + a.y * b.y + a.z * b.z + a.w * b.w;
    }
    for (int o = 16; o; o >>= 1) s += __shfl_xor_sync(0xffffffffu, s, o);
    if (lane == 0) {
        float sc = s + bp[wid];
        g_scores[n * C_ + wid] = sc;
        float t = (labels[n] == wid) ? 1.f : 0.f;
        float ce = fmaxf(sc, 0.f) - sc * t + log1pf(expf(-fabsf(sc)));
        float p = 1.f / (1.f + expf(-sc));
        float pt = p * t + (1.f - p) * (1.f - t);
        float at = 0.25f * t + 0.75f * (1.f - t);
        float om = 1.f - pt;
        terms[wid] = at * ce * om * om;
    }
    __syncthreads();
    if (threadIdx.x == 0) {
        float acc = 0.f;
#pragma unroll
        for (int c = 0; c < C_; c++) acc += terms[c];
        g_cls_part[n] = acc;
    }
}

// ---------------- per-class mean, stage 1: q-chunk partial sums ----------------
__global__ void k_mu_part(const float* __restrict__ idd, const float* __restrict__ box) {
    int c = blockIdx.x, chunk = blockIdx.y;
    int r = threadIdx.x;                  // 1024
    int kc = g_kc[c];
    int nold = Q_ - kc;
    float s = 0.f;
#pragma unroll 5
    for (int q2 = chunk * 125; q2 < (chunk + 1) * 125; q2++) {
        if (q2 < nold) s += idd[((size_t)c * Q_ + kc + q2) * R_ + r];
        else           s += box[(size_t)g_list[c * N_ + (q2 - nold)] * R_ + r];
    }
    g_mupart[(c * 8 + chunk) * R_ + r] = s;
}

// ---------------- per-class mean, stage 2 ----------------
__global__ void k_mu_fin() {
    int c = blockIdx.x; int r = threadIdx.x;
    float s = 0.f;
#pragma unroll
    for (int k = 0; k < 8; k++) s += g_mupart[(c * 8 + k) * R_ + r];
    g_mu[c * R_ + r] = s * (1.f / (float)Q_);
}

// ---------------- centered X ----------------
__global__ void k_buildX(const float* __restrict__ idd, const float* __restrict__ box) {
    int k = blockIdx.x;
    int c = k / Q_; int q = k - c * Q_;
    int kc = g_kc[c]; int q2 = q + kc;
    const float4* src;
    if (q2 < Q_) src = (const float4*)(idd + ((size_t)c * Q_ + q2) * R_);
    else         src = (const float4*)(box + (size_t)g_list[c * N_ + (q2 - Q_)] * R_);
    const float4* mu = (const float4*)(g_mu + c * R_);
    float4 v = src[threadIdx.x]; float4 m = mu[threadIdx.x];
    v.x -= m.x; v.y -= m.y; v.z -= m.z; v.w -= m.w;
    ((float4*)(g_X + (size_t)k * R_))[threadIdx.x] = v;
}

// ---------------- Gram X^T X: 128x128 lower-tri tiles, split-K, f32x2, reg-prefetch pipeline ----------------
__global__ void __launch_bounds__(256, 2) k_gram() {
    __shared__ float As[8][128], Bs[8][128];
    int t36 = blockIdx.x, kz = blockIdx.y;
    int ti, tj; tri_decode(t36, ti, tj);
    int tid = threadIdx.x;
    int kr = tid >> 5, cf = tid & 31;
    int tx = tid & 15, ty = tid >> 4;
    unsigned long long acc[8][4];
#pragma unroll
    for (int i = 0; i < 8; i++)
#pragma unroll
        for (int j = 0; j < 4; j++) acc[i][j] = 0ull;
    int k0 = kz * 1248;
    int klen = (kz == SPLITK - 1) ? 1264 : 1248;
    const float* XA = g_X + (size_t)ti * 128 + (size_t)(k0 + kr) * R_ + cf * 4;
    const float* XB = g_X + (size_t)tj * 128 + (size_t)(k0 + kr) * R_ + cf * 4;
    float4 ra = *(const float4*)XA;
    float4 rb = *(const float4*)XB;
    for (int kb = 0; kb < klen; kb += 8) {
        *(float4*)&As[kr][cf * 4] = ra;
        *(float4*)&Bs[kr][cf * 4] = rb;
        __syncthreads();
        XA += 8 * R_; XB += 8 * R_;
        if (kb + 8 < klen) { ra = *(const float4*)XA; rb = *(const float4*)XB; }
#pragma unroll
        for (int kk = 0; kk < 8; kk++) {
            F4U a0, a1, b0, b1;
            a0.f4 = *(float4*)&As[kk][ty * 8];
            a1.f4 = *(float4*)&As[kk][ty * 8 + 4];
            b0.f4 = *(float4*)&Bs[kk][tx * 8];
            b1.f4 = *(float4*)&Bs[kk][tx * 8 + 4];
            unsigned long long bu[4] = { b0.u[0], b0.u[1], b1.u[0], b1.u[1] };
#pragma unroll
            for (int i = 0; i < 4; i++) {
                unsigned long long ad0 = dup2(a0.f[i]);
                unsigned long long ad1 = dup2(a1.f[i]);
#pragma unroll
                for (int j = 0; j < 4; j++) {
                    fma2(acc[i][j], ad0, bu[j]);
                    fma2(acc[i + 4][j], ad1, bu[j]);
                }
            }
        }
        __syncthreads();
    }
    float* outp = g_Spart + (size_t)(kz * 36 + t36) * 16384;
#pragma unroll
    for (int i = 0; i < 8; i++)
#pragma unroll
        for (int j = 0; j < 4; j++) {
            unsigned long long v = acc[i][j];
            float lo = __uint_as_float((unsigned)(v & 0xffffffffull));
            float hi = __uint_as_float((unsigned)(v >> 32));
            outp[(ty * 8 + i) * 128 + tx * 8 + 2 * j] = lo;
            outp[(ty * 8 + i) * 128 + tx * 8 + 2 * j + 1] = hi;
        }
}

// ---------------- reduce partials -> sigma (symmetric, +eps I) ----------------
__global__ void k_gram_reduce() {
    int t36 = blockIdx.x;
    int ti, tj; tri_decode(t36, ti, tj);
    for (int e = 0; e < 64; e++) {
        int idx = e * 256 + threadIdx.x;
        int r = idx >> 7, c = idx & 127;
        float s = 0.f;
#pragma unroll
        for (int kz = 0; kz < SPLITK; kz++)
            s += g_Spart[(size_t)(kz * 36 + t36) * 16384 + idx];
        float val = s / 10000.f;
        int gi = ti * 128 + r, gj = tj * 128 + c;
        if (gi == gj) val += 1e-4f;
        g_S[(size_t)gi * R_ + gj] = val;
        g_S[(size_t)gj * R_ + gi] = val;
    }
}

// ---------------- Cholesky diag panel: column-major smem (stride 129), conflict-free ----------------
// Tc[col*129 + row] holds working element (row, col), col <= row (lower triangle).
__global__ void k_chol_diag(int p) {
    extern __shared__ float Tc[];       // 128*129 floats = 66048 B
    int base = p * 128;
    int tid = threadIdx.x;              // 512 threads
    int x = tid & 127, y = tid >> 7;    // y in 0..3
    // load: thread x owns column x; rows i >= x. Coalesced gmem reads, conflict-free smem.
    for (int i = y; i < 128; i += 4)
        if (x <= i) Tc[x * 129 + i] = g_S[(size_t)(base + i) * R_ + base + x];
    __syncthreads();
    for (int j = 0; j < 128; j++) {
        float inv = __fdividef(1.f, Tc[j * 129 + j]);
        if (x > j) {
            float lxj = Tc[j * 129 + x] * inv;     // element (x, j)
            for (int k = j + 1 + y; k <= x; k += 4)
                Tc[k * 129 + x] -= lxj * Tc[j * 129 + k];   // (x,k) -= lxj * (k,j)
        }
        __syncthreads();
    }
    // scale: L[i][x] = A[i][x] * rsqrt(d_x); write coalesced by row i
    for (int i = y; i < 128; i += 4)
        if (x <= i)
            g_S[(size_t)(base + i) * R_ + base + x] = Tc[x * 129 + i] * rsqrtf(Tc[x * 129 + x]);
}

// ---------------- trsm: smem-staged L11^T, barrier-free solve loop ----------------
__global__ void k_trsm(int p) {
    __shared__ float U[8256];     // packed: U[off(j)+(k-j)] = L[k][j], off(j)=j*128-j*(j-1)/2
    __shared__ float dinv[128];
    int base = p * 128;
    int tid = threadIdx.x;        // 256 threads
    int w = tid >> 5, lane = tid & 31;
    for (int k = w; k < 128; k += 8) {
        for (int j = lane; j <= k; j += 32) {
            int offj = j * 128 - (j * (j - 1)) / 2;
            U[offj + (k - j)] = g_S[(size_t)(base + k) * R_ + base + j];
        }
    }
    __syncthreads();
    if (tid < 128) {
        int offj = tid * 128 - (tid * (tid - 1)) / 2;
        dinv[tid] = __fdividef(1.f, U[offj]);
    }
    __syncthreads();
    int row = base + 128 + blockIdx.x * 8 + w;
    float* arow = g_S + (size_t)row * R_ + base;
    float a0 = arow[lane], a1 = arow[lane + 32], a2 = arow[lane + 64], a3 = arow[lane + 96];
    int offj = 0;
    for (int j = 0; j < 128; j++) {
        int src = j & 31, slot = j >> 5;
        float aval = (slot == 0) ? a0 : (slot == 1) ? a1 : (slot == 2) ? a2 : a3;
        float xj = __shfl_sync(0xffffffffu, aval, src) * dinv[j];
        if (lane == src) {
            if (slot == 0) a0 = xj; else if (slot == 1) a1 = xj;
            else if (slot == 2) a2 = xj; else a3 = xj;
        }
        if (lane > j)      a0 -= xj * U[offj + (lane - j)];
        if (lane + 32 > j) a1 -= xj * U[offj + (lane + 32 - j)];
        if (lane + 64 > j) a2 -= xj * U[offj + (lane + 64 - j)];
        if (lane + 96 > j) a3 -= xj * U[offj + (lane + 96 - j)];
        offj += 128 - j;
    }
    arow[lane] = a0; arow[lane + 32] = a1; arow[lane + 64] = a2; arow[lane + 96] = a3;
}

// ---------------- syrk trailing update (64x64 tiles) ----------------
__global__ void k_syrk(int p) {
    __shared__ float As[64][17], Bs[64][17];
    int base = p * 128, trail = base + 128;
    int ti, tj; tri_decode(blockIdx.x, ti, tj);
    int gi0 = trail + ti * 64, gj0 = trail + tj * 64;
    int tid = threadIdx.x;
    int tx = tid & 15, ty = tid >> 4;
    float acc[4][4];
#pragma unroll
    for (int r = 0; r < 4; r++)
#pragma unroll
        for (int s = 0; s < 4; s++) acc[r][s] = 0.f;
    for (int kc = 0; kc < 128; kc += 16) {
        int li = tid >> 2, lk = (tid & 3) * 4;
        float4 va = *(const float4*)&g_S[(size_t)(gi0 + li) * R_ + base + kc + lk];
        float4 vb = *(const float4*)&g_S[(size_t)(gj0 + li) * R_ + base + kc + lk];
        As[li][lk] = va.x; As[li][lk + 1] = va.y; As[li][lk + 2] = va.z; As[li][lk + 3] = va.w;
        Bs[li][lk] = vb.x; Bs[li][lk + 1] = vb.y; Bs[li][lk + 2] = vb.z; Bs[li][lk + 3] = vb.w;
        __syncthreads();
#pragma unroll
        for (int kk = 0; kk < 16; kk++) {
            float a[4], b[4];
#pragma unroll
            for (int r = 0; r < 4; r++) a[r] = As[ty * 4 + r][kk];
#pragma unroll
            for (int s = 0; s < 4; s++) b[s] = Bs[tx * 4 + s][kk];
#pragma unroll
            for (int r = 0; r < 4; r++)
#pragma unroll
                for (int s = 0; s < 4; s++) acc[r][s] += a[r] * b[s];
        }
        __syncthreads();
    }
#pragma unroll
    for (int r = 0; r < 4; r++)
#pragma unroll
        for (int s = 0; s < 4; s++)
            g_S[(size_t)(gi0 + ty * 4 + r) * R_ + gj0 + tx * 4 + s] -= acc[r][s];
}

// ---------------- eps argmax of ||eps[c,s]||^2 (warp per row, streaming loads) ----------------
__global__ void k_eps(const float* __restrict__ eps) {
    int w = blockIdx.x * 8 + (threadIdx.x >> 5);
    int lane = threadIdx.x & 31;
    int c = w / S_, s = w - c * S_;
    const float4* row = (const float4*)(eps + (size_t)w * R_);
    float acc = 0.f;
#pragma unroll
    for (int i = 0; i < 8; i++) {
        float4 v = __ldcs(&row[lane + i * 32]);
        acc += v.x * v.x + v.y * v.y + v.z * v.z + v.w * v.w;
    }
    for (int o = 16; o; o >>= 1) acc += __shfl_xor_sync(0xffffffffu, acc, o);
    if (lane == 0) {
        unsigned long long key = ((unsigned long long)__float_as_uint(acc) << 32)
                               | (unsigned long long)(0x7FFFFFFFu - (unsigned)s);
        atomicMax(&g_amax[c], key);
    }
}

// ---------------- vos = mu + L @ eps_sel (warp per output element) ----------------
__global__ void k_vos(const float* __restrict__ eps) {
    int c = blockIdx.y;
    int r = blockIdx.x * 8 + (threadIdx.x >> 5);
    int lane = threadIdx.x & 31;
    int idx = 0x7FFFFFFF - (int)(unsigned)(g_amax[c] & 0xffffffffull);
    const float* erow = eps + ((size_t)c * S_ + idx) * R_;
    const float* Lr = g_S + (size_t)r * R_;
    float s = 0.f;
    for (int j = lane; j <= r; j += 32) s += erow[j] * Lr[j];
    for (int o = 16; o; o >>= 1) s += __shfl_xor_sync(0xffffffffu, s, o);
    if (lane == 0) g_vos[c * R_ + r] = g_mu[c * R_ + r] + s;
}

// ---------------- scores_vos ----------------
__global__ void k_svos(const float* __restrict__ Wp, const float* __restrict__ bp) {
    int i = blockIdx.x, j = blockIdx.y;
    int tid = threadIdx.x;
    __shared__ float ws[4];
    float s = 0.f;
    for (int r = tid; r < R_; r += 128) s += g_vos[i * R_ + r] * Wp[(size_t)j * R_ + r];
    for (int o = 16; o; o >>= 1) s += __shfl_xor_sync(0xffffffffu, s, o);
    if ((tid & 31) == 0) ws[tid >> 5] = s;
    __syncthreads();
    if (tid == 0) g_svos[i * C_ + j] = ws[0] + ws[1] + ws[2] + ws[3] + bp[j];
}

// ---------------- energy + MLP + BCE (warp per item) ----------------
__global__ void k_energy(const float* __restrict__ we, const float* __restrict__ W1,
                         const float* __restrict__ b1, const float* __restrict__ W2,
                         const float* __restrict__ b2) {
    int item = blockIdx.x * 8 + (threadIdx.x >> 5);
    int lane = threadIdx.x & 31;
    if (item >= N_ + C_) return;
    float x = -1e30f;
    if (lane < C_) x = (item < N_) ? g_scores[item * C_ + lane] : g_svos[(item - N_) * C_ + lane];
    float m = x;
    for (int o = 16; o; o >>= 1) m = fmaxf(m, __shfl_xor_sync(0xffffffffu, m, o));
    float t = (lane < C_) ? expf(x - m) * fmaxf(we[lane], 0.f) : 0.f;
    for (int o = 16; o; o >>= 1) t += __shfl_xor_sync(0xffffffffu, t, o);
    float e = m + logf(t);
    float acc = 0.f;
    for (int j = lane; j < 512; j += 32) acc += fmaxf(e * W1[j] + b1[j], 0.f) * W2[j];
    for (int o = 16; o; o >>= 1) acc += __shfl_xor_sync(0xffffffffu, acc, o);
    if (lane == 0) {
        float l = acc + b2[0];
        float y = (item < N_) ? 1.f : 0.f;
        g_bce[item] = fmaxf(l, 0.f) - l * y + log1pf(expf(-fabsf(l)));
    }
}

// ---------------- final reduction (parallel; folds the 10 tail items) ----------------
__global__ void k_final(float* __restrict__ out) {
    __shared__ float sc[16], sd[16];
    int tid = threadIdx.x;               // 512
    int w = tid >> 5, lane = tid & 31;
    float a = g_cls_part[tid];
    float b = g_bce[tid] + ((tid < C_) ? g_bce[N_ + tid] : 0.f);
    for (int o = 16; o; o >>= 1) { a += __shfl_xor_sync(0xffffffffu, a, o); b += __shfl_xor_sync(0xffffffffu, b, o); }
    if (lane == 0) { sc[w] = a; sd[w] = b; }
    __syncthreads();
    if (tid == 0) {
        float cs = 0.f, ds = 0.f;
#pragma unroll
        for (int i = 0; i < 16; i++) { cs += sc[i]; ds += sd[i]; }
        out[0] = cs / (float)N_;
        out[1] = 0.1f * ds / (float)(N_ + C_);
    }
}

extern "C" void kernel_launch(void* const* d_in, const int* in_sizes, int n_in,
                              void* d_out, int out_size) {
    const float* box = (const float*)d_in[0];
    const int* labels = (const int*)d_in[1];
    const float* idd = (const float*)d_in[2];
    const float* Wp = (const float*)d_in[4];
    const float* bp = (const float*)d_in[5];
    const float* we = (const float*)d_in[6];
    const float* W1 = (const float*)d_in[7];
    const float* b1 = (const float*)d_in[8];
    const float* W2 = (const float*)d_in[9];
    const float* b2 = (const float*)d_in[10];
    const float* eps = (const float*)d_in[11];
    float* out = (float*)d_out;

    cudaFuncSetAttribute(k_chol_diag, cudaFuncAttributeMaxDynamicSharedMemorySize, 128 * 129 * 4);

    k_lists<<<1, 512>>>(labels);
    k_scores_cls<<<N_, 320>>>(box, Wp, bp, labels);
    k_mu_part<<<dim3(C_, 8), 1024>>>(idd, box);
    k_mu_fin<<<C_, 1024>>>();
    k_buildX<<<CQ, 256>>>(idd, box);
    k_gram<<<dim3(36, SPLITK), 256>>>();
    k_gram_reduce<<<36, 256>>>();
    for (int p = 0; p < 8; p++) {
        k_chol_diag<<<1, 512, 128 * 129 * 4>>>(p);
        int nrows = R_ - (p + 1) * 128;
        if (nrows > 0) {
            k_trsm<<<nrows / 8, 256>>>(p);
            int T = nrows / 64;
            k_syrk<<<T * (T + 1) / 2, 256>>>(p);
        }
    }
    k_eps<<<(C_ * S_) / 8, 256>>>(eps);
    k_vos<<<dim3(128, C_), 256>>>(eps);
    k_svos<<<dim3(C_, C_), 128>>>(Wp, bp);
    k_energy<<<(N_ + C_ + 7) / 8, 256>>>(we, W1, b1, W2, b2);
    k_final<<<1, 512>>>(out);
}